// round 13
// baseline (speedup 1.0000x reference)
#include <cuda_runtime.h>
#include <math.h>

#define EPS_F 1e-8f
#define MAXB  2048
#define SENT  1000000.0f

__device__ float    g_partials[MAXB];
__device__ unsigned g_count = 0;   // atomicInc wraps -> identical state every graph replay

// Monotone-in-atan2 pseudo angle over (-pi, pi].
__device__ __forceinline__ float pseudo_angle(float x, float y) {
    float r = __fdividef(x, fabsf(x) + fabsf(y));
    return (y >= 0.0f) ? (1.0f - r) : (r - 1.0f);
}

// compare-exchange on (key, vx, vy), ascending by key
#define CE(a, b) { bool sw_ = key[a] > key[b];                              \
    float t0_ = sw_ ? key[b] : key[a]; key[b] = sw_ ? key[a] : key[b]; key[a] = t0_; \
    float t1_ = sw_ ? vx[b]  : vx[a];  vx[b]  = sw_ ? vx[a]  : vx[b];  vx[a]  = t1_; \
    float t2_ = sw_ ? vy[b]  : vy[a];  vy[b]  = sw_ ? vy[a]  : vy[b];  vy[a]  = t2_; }

__global__ void __launch_bounds__(256)
rotated_iou_loss_kernel(const float* __restrict__ pred,
                        const float* __restrict__ targ,
                        const float* __restrict__ wgt,
                        float* __restrict__ out, int N) {
    __shared__ float sp[256 * 7];
    __shared__ float sq[256 * 7];
    float acc = 0.0f;
    const int stride = gridDim.x * blockDim.x;

    for (int base = blockIdx.x * blockDim.x; base < N; base += stride) {
        // ---- coalesced stage of the stride-7 inputs through smem ----
        __syncthreads();
        {
            int gbase = base * 7;
            int lim = N * 7;
            #pragma unroll
            for (int k = threadIdx.x; k < 256 * 7; k += 256) {
                int g = gbase + k;
                if (g < lim) { sp[k] = pred[g]; sq[k] = targ[g]; }
            }
        }
        __syncthreads();

        int i = base + threadIdx.x;
        if (i < N) {
            float p[7], q[7];
            #pragma unroll
            for (int k = 0; k < 7; k++) {
                p[k] = sp[threadIdx.x * 7 + k];
                q[k] = sq[threadIdx.x * 7 + k];
            }

            // ---- decode_fcos_obb (loc = 0) ----
            float w1 = p[0] + p[3], l1 = p[1] + p[4], h1 = p[2] + p[5];
            float s1, c1;  __sincosf(p[6], &s1, &c1);
            float ox1 = 0.5f * (p[3] - p[0]), oy1 = 0.5f * (p[4] - p[1]);
            float cx1 = ox1 * c1 - oy1 * s1, cy1 = ox1 * s1 + oy1 * c1;
            float cz1 = 0.5f * (p[5] - p[2]);

            float w2 = q[0] + q[3], l2 = q[1] + q[4], h2 = q[2] + q[5];
            float s2, c2;  __sincosf(q[6], &s2, &c2);
            float ox2 = 0.5f * (q[3] - q[0]), oy2 = 0.5f * (q[4] - q[1]);
            float cx2 = ox2 * c2 - oy2 * s2, cy2 = ox2 * s2 + oy2 * c2;
            float cz2 = 0.5f * (q[5] - q[2]);

            float hw1 = 0.5f * w1, hl1 = 0.5f * l1;
            float hw2 = 0.5f * w2, hl2 = 0.5f * l2;

            // ---- box1 local frame: box1 axis-aligned at origin ----
            // center of box2 in frame1
            float rxc = cx2 - cx1, ryc = cy2 - cy1;
            float C2x =  c1 * rxc + s1 * ryc;
            float C2y = -s1 * rxc + c1 * ryc;
            // box2 axes in frame1: rotation by (theta2 - theta1)
            float ct = c1 * c2 + s1 * s2;
            float st = c1 * s2 - s1 * c2;

            // A corners (frame1, axis-aligned), B corners (frame1)
            const float SGX[4] = {1.0f, -1.0f, -1.0f, 1.0f};
            const float SGY[4] = {1.0f, 1.0f, -1.0f, -1.0f};
            float axr[4], ayr[4], bxr[4], byr[4];
            #pragma unroll
            for (int k = 0; k < 4; k++) {
                axr[k] = SGX[k] * hw1;
                ayr[k] = SGY[k] * hl1;
                float X = SGX[k] * hw2, Y = SGY[k] * hl2;
                bxr[k] = C2x + X * ct - Y * st;
                byr[k] = C2y + X * st + Y * ct;
            }

            // ---- candidate collection into 8 slots (polygon has <= 8 verts) ----
            float2 s8[8];
            int cnt = 0;
            float sx = 0.0f, sy = 0.0f;
            const float tol = 1e-6f;

            auto push = [&](float px, float py) {
                if (cnt < 8) { s8[cnt] = make_float2(px, py); sx += px; sy += py; cnt++; }
            };

            // A corners inside box2: axis-aligned test in frame2
            {
                float tw2 = tol * w2, tl2 = tol * l2;
                #pragma unroll
                for (int k = 0; k < 4; k++) {
                    float du = axr[k] - C2x, dv = ayr[k] - C2y;
                    float u =  ct * du + st * dv;     // coord in frame2
                    float v = -st * du + ct * dv;
                    float tu = hw2 - u, tv = hl2 - v; // p_ab*w2, p_ad*l2
                    bool f = (tu > -tw2) & (tu < w2 + tw2) &
                             (tv > -tl2) & (tv < l2 + tl2);
                    if (f) push(axr[k], ayr[k]);
                }
            }
            // B corners inside box1: axis-aligned test in frame1
            {
                float tw1 = tol * w1, tl1 = tol * l1;
                #pragma unroll
                for (int k = 0; k < 4; k++) {
                    float tu = hw1 - bxr[k], tv = hl1 - byr[k];
                    bool f = (tu > -tw1) & (tu < w1 + tw1) &
                             (tv > -tl1) & (tv < l1 + tl1);
                    if (f) push(bxr[k], byr[k]);
                }
            }

            // A-edge x B-edge intersections; A edges are axis-aligned in frame1.
            // Same sign-folded mask + t2 = den_t/(num+EPS) semantics as reference.
            // horizontal A-edge: start (x1, Y0), direction (D, 0)
            auto isect_h = [&](float x1, float Y0, float D) {
                #pragma unroll
                for (int jj = 0; jj < 4; jj++) {
                    int j1 = (jj + 1) & 3;
                    float x3 = bxr[jj], y3 = byr[jj];
                    float dx43 = bxr[j1] - x3, dy43 = byr[j1] - y3;
                    float num   = dy43 * D;
                    float rx = x1 - x3, ry = Y0 - y3;
                    float den_t = dx43 * ry - dy43 * rx;
                    float den_u = D * ry;
                    bool m;
                    if (num > 0.0f)
                        m = (den_t > 0.0f) & (den_t < num) & (den_u < 0.0f) & (den_u > -num);
                    else if (num < 0.0f)
                        m = (den_t < 0.0f) & (den_t > num) & (den_u > 0.0f) & (den_u < -num);
                    else
                        m = false;
                    if (m) {
                        float t2 = __fdividef(den_t, num + EPS_F);
                        push(x1 + t2 * D, Y0);
                    }
                }
            };
            // vertical A-edge: start (X0, y1), direction (0, L)
            auto isect_v = [&](float X0, float y1, float L) {
                #pragma unroll
                for (int jj = 0; jj < 4; jj++) {
                    int j1 = (jj + 1) & 3;
                    float x3 = bxr[jj], y3 = byr[jj];
                    float dx43 = bxr[j1] - x3, dy43 = byr[j1] - y3;
                    float num   = -dx43 * L;
                    float rx = X0 - x3, ry = y1 - y3;
                    float den_t = dx43 * ry - dy43 * rx;
                    float den_u = -L * rx;
                    bool m;
                    if (num > 0.0f)
                        m = (den_t > 0.0f) & (den_t < num) & (den_u < 0.0f) & (den_u > -num);
                    else if (num < 0.0f)
                        m = (den_t < 0.0f) & (den_t > num) & (den_u > 0.0f) & (den_u < -num);
                    else
                        m = false;
                    if (m) {
                        float t2 = __fdividef(den_t, num + EPS_F);
                        push(X0, y1 + t2 * L);
                    }
                }
            };
            isect_h( hw1,  hl1, -w1);   // A0 -> A1
            isect_v(-hw1,  hl1, -l1);   // A1 -> A2
            isect_h(-hw1, -hl1,  w1);   // A2 -> A3
            isect_v( hw1, -hl1,  l1);   // A3 -> A0

            // ---- centroid, keys, 8-wide sorting network, padded ring ----
            float fc = (float)(cnt > 0 ? cnt : 1);
            float mx = __fdividef(sx, fc), my = __fdividef(sy, fc);

            float key[8], vx[8], vy[8];
            #pragma unroll
            for (int j = 0; j < 8; j++) {
                bool val = (j < cnt);
                float2 w = s8[j];
                float X = w.x - mx, Y = w.y - my;
                vx[j] = X; vy[j] = Y;
                key[j] = val ? pseudo_angle(X, Y) : SENT;
            }
            // optimal 19-CE network for n = 8 (ascending)
            CE(0,1) CE(2,3) CE(4,5) CE(6,7)
            CE(0,2) CE(1,3) CE(4,6) CE(5,7)
            CE(1,2) CE(5,6) CE(0,4) CE(3,7)
            CE(1,5) CE(2,6)
            CE(1,4) CE(3,6)
            CE(2,4) CE(3,5)
            CE(3,4)
            // replace sentinel slots with the first vertex (reference padding)
            {
                float fx = vx[0], fy = vy[0];
                #pragma unroll
                for (int j = 1; j < 8; j++) {
                    bool inv = key[j] >= SENT;
                    vx[j] = inv ? fx : vx[j];
                    vy[j] = inv ? fy : vy[j];
                }
            }
            float cr = 0.0f;
            #pragma unroll
            for (int j = 0; j < 8; j++) {
                int j1 = (j + 1) & 7;
                cr += vx[j] * vy[j1] - vy[j] * vx[j1];
            }
            float inter = (cnt >= 3) ? 0.5f * fabsf(cr) : 0.0f;

            // ---- 3D: z overlap, volumes, loss ----
            float zt = fminf(cz1 + 0.5f * h1, cz2 + 0.5f * h2);
            float zb = fmaxf(cz1 - 0.5f * h1, cz2 - 0.5f * h2);
            float zo = fmaxf(zt - zb, 0.0f);
            float inter3d = inter * zo;        // iou2d * u2d * z == inter * z
            float u3d = w1 * l1 * h1 + w2 * l2 * h2 - inter3d;
            float iou = __fdividef(inter3d + 1.0f, u3d + 1.0f);
            acc += -__logf(iou) * wgt[i];
        }
    }

    // ---- block reduction ----
    #pragma unroll
    for (int o = 16; o; o >>= 1) acc += __shfl_down_sync(0xffffffffu, acc, o);
    __shared__ float sh[8];
    int lane = threadIdx.x & 31, warp = threadIdx.x >> 5;
    if (lane == 0) sh[warp] = acc;
    __syncthreads();
    if (threadIdx.x < 8) {
        float vsum = sh[threadIdx.x];
        #pragma unroll
        for (int o = 4; o; o >>= 1) vsum += __shfl_down_sync(0xffu, vsum, o);
        if (threadIdx.x == 0) g_partials[blockIdx.x] = vsum;
    }

    // ---- last-block final reduction (deterministic, single kernel) ----
    __shared__ bool is_last;
    __threadfence();
    if (threadIdx.x == 0) {
        unsigned prev = atomicInc(&g_count, gridDim.x - 1); // wraps to 0 on last
        is_last = (prev == gridDim.x - 1);
    }
    __syncthreads();
    if (is_last) {
        float vsum = 0.0f;
        for (int k = threadIdx.x; k < (int)gridDim.x; k += blockDim.x)
            vsum += g_partials[k];
        #pragma unroll
        for (int o = 16; o; o >>= 1) vsum += __shfl_down_sync(0xffffffffu, vsum, o);
        if (lane == 0) sh[warp] = vsum;
        __syncthreads();
        if (threadIdx.x < 8) {
            float x = sh[threadIdx.x];
            #pragma unroll
            for (int o = 4; o; o >>= 1) x += __shfl_down_sync(0xffu, x, o);
            if (threadIdx.x == 0) out[0] = x;
        }
    }
}

extern "C" void kernel_launch(void* const* d_in, const int* in_sizes, int n_in,
                              void* d_out, int out_size) {
    const float* pred = (const float*)d_in[0];
    const float* targ = (const float*)d_in[1];
    const float* wgt  = (const float*)d_in[2];
    int N = (n_in >= 3) ? in_sizes[2] : in_sizes[0] / 7;
    const int threads = 256;
    int blocks = (N + threads - 1) / threads;
    if (blocks > MAXB) blocks = MAXB;
    rotated_iou_loss_kernel<<<blocks, threads>>>(pred, targ, wgt, (float*)d_out, N);
}

// round 14
// speedup vs baseline: 1.1314x; 1.1314x over previous
#include <cuda_runtime.h>
#include <math.h>

#define EPS_F 1e-8f
#define MAXB  2048
#define SENT  1000000.0f

__device__ float    g_partials[MAXB];
__device__ unsigned g_count = 0;   // atomicInc wraps -> identical state every graph replay

// Monotone-in-atan2 pseudo angle over (-pi, pi].
__device__ __forceinline__ float pseudo_angle(float x, float y) {
    float r = __fdividef(x, fabsf(x) + fabsf(y));
    return (y >= 0.0f) ? (1.0f - r) : (r - 1.0f);
}

// payload-free compare-exchange (keys only, FMNMX pair)
#define CE(a, b) { float lo_ = fminf(key[a], key[b]);                \
                   float hi_ = fmaxf(key[a], key[b]);                \
                   key[a] = lo_; key[b] = hi_; }

__global__ void __launch_bounds__(256)
rotated_iou_loss_kernel(const float* __restrict__ pred,
                        const float* __restrict__ targ,
                        const float* __restrict__ wgt,
                        float* __restrict__ out, int N) {
    __shared__ float  sp[256 * 7];
    __shared__ float  sq[256 * 7];
    __shared__ float2 spoly[8][256];   // slot-major: conflict-free per-thread access
    float acc = 0.0f;
    const int stride = gridDim.x * blockDim.x;

    for (int base = blockIdx.x * blockDim.x; base < N; base += stride) {
        // ---- coalesced stage of the stride-7 inputs through smem ----
        __syncthreads();
        {
            int gbase = base * 7;
            int lim = N * 7;
            #pragma unroll
            for (int k = threadIdx.x; k < 256 * 7; k += 256) {
                int g = gbase + k;
                if (g < lim) { sp[k] = pred[g]; sq[k] = targ[g]; }
            }
        }
        __syncthreads();

        int i = base + threadIdx.x;
        if (i < N) {
            float p[7], q[7];
            #pragma unroll
            for (int k = 0; k < 7; k++) {
                p[k] = sp[threadIdx.x * 7 + k];
                q[k] = sq[threadIdx.x * 7 + k];
            }

            // ---- decode_fcos_obb (loc = 0) ----
            float w1 = p[0] + p[3], l1 = p[1] + p[4], h1 = p[2] + p[5];
            float s1, c1;  __sincosf(p[6], &s1, &c1);
            float ox1 = 0.5f * (p[3] - p[0]), oy1 = 0.5f * (p[4] - p[1]);
            float cx1 = ox1 * c1 - oy1 * s1, cy1 = ox1 * s1 + oy1 * c1;
            float cz1 = 0.5f * (p[5] - p[2]);

            float w2 = q[0] + q[3], l2 = q[1] + q[4], h2 = q[2] + q[5];
            float s2, c2;  __sincosf(q[6], &s2, &c2);
            float ox2 = 0.5f * (q[3] - q[0]), oy2 = 0.5f * (q[4] - q[1]);
            float cx2 = ox2 * c2 - oy2 * s2, cy2 = ox2 * s2 + oy2 * c2;
            float cz2 = 0.5f * (q[5] - q[2]);

            // ---- box2corners (registers, static indexing) ----
            float ax[4], ay[4], bx[4], by[4];
            {
                const float SX[4] = {0.5f, -0.5f, -0.5f, 0.5f};
                const float SY[4] = {0.5f, 0.5f, -0.5f, -0.5f};
                #pragma unroll
                for (int k = 0; k < 4; k++) {
                    float X = SX[k] * w1, Y = SY[k] * l1;
                    ax[k] = X * c1 - Y * s1 + cx1;
                    ay[k] = X * s1 + Y * c1 + cy1;
                    X = SX[k] * w2; Y = SY[k] * l2;
                    bx[k] = X * c2 - Y * s2 + cx2;
                    by[k] = X * s2 + Y * c2 + cy2;
                }
            }

            // ---- candidate collection into 8 smem slots ----
            int cnt = 0;
            float sx = 0.0f, sy = 0.0f;
            const float tol = 1e-6f;

            // corners of box1 inside box2
            {
                float abx = bx[1] - bx[0], aby = by[1] - by[0];
                float adx = bx[3] - bx[0], ady = by[3] - by[0];
                float iab = __frcp_rn(abx * abx + aby * aby);
                float iad = __frcp_rn(adx * adx + ady * ady);
                #pragma unroll
                for (int k = 0; k < 4; k++) {
                    float amx = ax[k] - bx[0], amy = ay[k] - by[0];
                    float pab = (abx * amx + aby * amy) * iab;
                    float pad = (adx * amx + ady * amy) * iad;
                    bool f = (pab > -tol) & (pab < 1.0f + tol) &
                             (pad > -tol) & (pad < 1.0f + tol);
                    if (f && cnt < 8) {
                        spoly[cnt][threadIdx.x] = make_float2(ax[k], ay[k]);
                        sx += ax[k]; sy += ay[k]; cnt++;
                    }
                }
            }
            // corners of box2 inside box1
            {
                float abx = ax[1] - ax[0], aby = ay[1] - ay[0];
                float adx = ax[3] - ax[0], ady = ay[3] - ay[0];
                float iab = __frcp_rn(abx * abx + aby * aby);
                float iad = __frcp_rn(adx * adx + ady * ady);
                #pragma unroll
                for (int k = 0; k < 4; k++) {
                    float amx = bx[k] - ax[0], amy = by[k] - ay[0];
                    float pab = (abx * amx + aby * amy) * iab;
                    float pad = (adx * amx + ady * amy) * iad;
                    bool f = (pab > -tol) & (pab < 1.0f + tol) &
                             (pad > -tol) & (pad < 1.0f + tol);
                    if (f && cnt < 8) {
                        spoly[cnt][threadIdx.x] = make_float2(bx[k], by[k]);
                        sx += bx[k]; sy += by[k]; cnt++;
                    }
                }
            }
            // edge-edge intersections (division-free mask, exact sign logic of ref)
            #pragma unroll
            for (int ii = 0; ii < 4; ii++) {
                float x1 = ax[ii], y1 = ay[ii];
                float x2 = ax[(ii + 1) & 3], y2 = ay[(ii + 1) & 3];
                float dx21 = x2 - x1, dy21 = y2 - y1;
                #pragma unroll
                for (int jj = 0; jj < 4; jj++) {
                    float x3 = bx[jj], y3 = by[jj];
                    float x4 = bx[(jj + 1) & 3], y4 = by[(jj + 1) & 3];
                    float dx43 = x4 - x3, dy43 = y4 - y3;
                    float num   = dy43 * dx21 - dx43 * dy21;
                    float rx = x1 - x3, ry = y1 - y3;
                    float den_t = dx43 * ry - dy43 * rx;
                    float den_u = dx21 * ry - dy21 * rx;
                    bool m;
                    if (num > 0.0f)
                        m = (den_t > 0.0f) & (den_t < num) & (den_u < 0.0f) & (den_u > -num);
                    else if (num < 0.0f)
                        m = (den_t < 0.0f) & (den_t > num) & (den_u > 0.0f) & (den_u < -num);
                    else
                        m = false;
                    if (m && cnt < 8) {
                        float t2 = __fdividef(den_t, num + EPS_F);
                        float px = x1 + t2 * dx21, py = y1 + t2 * dy21;
                        spoly[cnt][threadIdx.x] = make_float2(px, py);
                        sx += px; sy += py; cnt++;
                    }
                }
            }

            // ---- keys with embedded slot index, payload-free sort, gather ----
            float fc = (float)(cnt > 0 ? cnt : 1);
            float mx = __fdividef(sx, fc), my = __fdividef(sy, fc);

            float key[8];
            #pragma unroll
            for (int j = 0; j < 8; j++) {
                float2 w = spoly[j][threadIdx.x];          // static slot index
                float kf = (j < cnt) ? pseudo_angle(w.x - mx, w.y - my) : SENT;
                key[j] = __uint_as_float((__float_as_uint(kf) & ~7u) | (unsigned)j);
            }
            // optimal 19-CE network for n = 8 (ascending, keys only)
            CE(0,1) CE(2,3) CE(4,5) CE(6,7)
            CE(0,2) CE(1,3) CE(4,6) CE(5,7)
            CE(1,2) CE(5,6) CE(0,4) CE(3,7)
            CE(1,5) CE(2,6)
            CE(1,4) CE(3,6)
            CE(2,4) CE(3,5)
            CE(3,4)

            // gather by embedded index (conflict-free dynamic LDS), pad invalid
            float2 ring[8];
            #pragma unroll
            for (int j = 0; j < 8; j++) {
                int id = (int)(__float_as_uint(key[j]) & 7u);
                ring[j] = spoly[id][threadIdx.x];
            }
            {
                float2 f0 = ring[0];
                #pragma unroll
                for (int j = 1; j < 8; j++) {
                    bool inv = key[j] >= 100.0f;           // sentinel slots
                    ring[j].x = inv ? f0.x : ring[j].x;
                    ring[j].y = inv ? f0.y : ring[j].y;
                }
            }
            // shoelace (cyclic sum is translation-invariant; no centering needed)
            float cr = 0.0f;
            #pragma unroll
            for (int j = 0; j < 8; j++) {
                int j1 = (j + 1) & 7;
                cr += ring[j].x * ring[j1].y - ring[j].y * ring[j1].x;
            }
            float inter = (cnt >= 3) ? 0.5f * fabsf(cr) : 0.0f;

            // ---- 3D: z overlap, volumes, loss ----
            float zt = fminf(cz1 + 0.5f * h1, cz2 + 0.5f * h2);
            float zb = fmaxf(cz1 - 0.5f * h1, cz2 - 0.5f * h2);
            float zo = fmaxf(zt - zb, 0.0f);
            float inter3d = inter * zo;        // iou2d * u2d * z == inter * z
            float u3d = w1 * l1 * h1 + w2 * l2 * h2 - inter3d;
            float iou = __fdividef(inter3d + 1.0f, u3d + 1.0f);
            acc += -__logf(iou) * wgt[i];
        }
    }

    // ---- block reduction ----
    #pragma unroll
    for (int o = 16; o; o >>= 1) acc += __shfl_down_sync(0xffffffffu, acc, o);
    __shared__ float sh[8];
    int lane = threadIdx.x & 31, warp = threadIdx.x >> 5;
    if (lane == 0) sh[warp] = acc;
    __syncthreads();
    if (threadIdx.x < 8) {
        float vsum = sh[threadIdx.x];
        #pragma unroll
        for (int o = 4; o; o >>= 1) vsum += __shfl_down_sync(0xffu, vsum, o);
        if (threadIdx.x == 0) g_partials[blockIdx.x] = vsum;
    }

    // ---- last-block final reduction (deterministic, single kernel) ----
    __shared__ bool is_last;
    __threadfence();
    if (threadIdx.x == 0) {
        unsigned prev = atomicInc(&g_count, gridDim.x - 1); // wraps to 0 on last
        is_last = (prev == gridDim.x - 1);
    }
    __syncthreads();
    if (is_last) {
        float vsum = 0.0f;
        for (int k = threadIdx.x; k < (int)gridDim.x; k += blockDim.x)
            vsum += g_partials[k];
        #pragma unroll
        for (int o = 16; o; o >>= 1) vsum += __shfl_down_sync(0xffffffffu, vsum, o);
        if (lane == 0) sh[warp] = vsum;
        __syncthreads();
        if (threadIdx.x < 8) {
            float x = sh[threadIdx.x];
            #pragma unroll
            for (int o = 4; o; o >>= 1) x += __shfl_down_sync(0xffu, x, o);
            if (threadIdx.x == 0) out[0] = x;
        }
    }
}

extern "C" void kernel_launch(void* const* d_in, const int* in_sizes, int n_in,
                              void* d_out, int out_size) {
    const float* pred = (const float*)d_in[0];
    const float* targ = (const float*)d_in[1];
    const float* wgt  = (const float*)d_in[2];
    int N = (n_in >= 3) ? in_sizes[2] : in_sizes[0] / 7;
    const int threads = 256;
    int blocks = (N + threads - 1) / threads;
    if (blocks > MAXB) blocks = MAXB;
    rotated_iou_loss_kernel<<<blocks, threads>>>(pred, targ, wgt, (float*)d_out, N);
}